// round 1
// baseline (speedup 1.0000x reference)
#include <cuda_runtime.h>

#define BATCH 64
#define SEQ   512
#define DIN   256
#define UNITS 512

// ---- scan partitioning ----
#define CB   16                 // batch groups
#define CN   8                  // column groups
#define BPG  (BATCH/CB)         // 4 batches per CTA
#define CPG  (UNITS/CN)         // 64 columns per CTA
#define NT   256                // threads per CTA

typedef unsigned long long ull;

// h state: [group][unit][4 batch values]  (float4 per unit)
__device__ float4 g_h[CB][UNITS];
__device__ int    g_bar[CB];

__device__ __forceinline__ ull f2pack(float x, float y) {
    ull r; asm("mov.b64 %0, {%1, %2};" : "=l"(r) : "f"(x), "f"(y)); return r;
}
__device__ __forceinline__ ull f2fma(ull a, ull b, ull c) {
    ull d; asm("fma.rn.f32x2 %0, %1, %2, %3;" : "=l"(d) : "l"(a), "l"(b), "l"(c)); return d;
}
__device__ __forceinline__ float2 f2unpack(ull a) {
    float2 v; asm("mov.b64 {%0, %1}, %2;" : "=f"(v.x), "=f"(v.y) : "l"(a)); return v;
}

// ============================================================================
// Kernel A: xT[t][b][u] = sum_d x[b][t][d] * T[d][u], written into d_out.
// Row r = t*64 + b  (matches output layout [seq, batch, units]).
// Classic 128x64 tile sgemm with f32x2 packed FMA. Also resets the scan
// barrier counters and seeds g_h with h0.
// ============================================================================
__global__ __launch_bounds__(NT) void proj_kernel(
    const float* __restrict__ x, const float* __restrict__ T,
    const float* __restrict__ h0, float* __restrict__ out)
{
    const int tid = threadIdx.x;

    if (blockIdx.y == 0) {
        if (blockIdx.x == 0 && tid < CB) g_bar[tid] = 0;
        if (blockIdx.x == 1) {
            float* gh = (float*)g_h;
            for (int i = tid; i < CB * UNITS * BPG; i += NT) {
                int k = (i >> 2) & (UNITS - 1);
                gh[i] = h0[k];
            }
        }
    }

    __shared__ float As[16][136];   // padded: conflict-free transposed stores
    __shared__ float Bs[16][64];

    const int tx = tid & 15, ty = tid >> 4;
    const int m0 = ty * 8, n0 = tx * 4;
    const int rowbase = blockIdx.y * 128;
    const int nbase   = blockIdx.x * 64;

    ull acc[8][2];
    #pragma unroll
    for (int i = 0; i < 8; i++) { acc[i][0] = 0ull; acc[i][1] = 0ull; }

    for (int kt = 0; kt < DIN; kt += 16) {
        // A tile: 128 rows x 16 k  (gather: row r -> x[b=r&63][t=r>>6][.])
        #pragma unroll
        for (int l = 0; l < 2; l++) {
            int idx = tid + l * NT;
            int row = idx >> 2, kq = idx & 3;
            int r = rowbase + row;
            int b = r & 63, t = r >> 6;
            float4 v = *(const float4*)(x + (size_t)(b * SEQ + t) * DIN + kt + kq * 4);
            As[kq * 4 + 0][row] = v.x;
            As[kq * 4 + 1][row] = v.y;
            As[kq * 4 + 2][row] = v.z;
            As[kq * 4 + 3][row] = v.w;
        }
        // B tile: 16 rows x 64 cols of T
        {
            int rr = tid >> 4, q = tid & 15;
            *(float4*)&Bs[rr][q * 4] =
                *(const float4*)(T + (size_t)(kt + rr) * UNITS + nbase + q * 4);
        }
        __syncthreads();
        #pragma unroll
        for (int k = 0; k < 16; k++) {
            float4 a0 = *(float4*)&As[k][m0];
            float4 a1 = *(float4*)&As[k][m0 + 4];
            float4 bv = *(float4*)&Bs[k][n0];
            ull b01 = f2pack(bv.x, bv.y);
            ull b23 = f2pack(bv.z, bv.w);
            float am[8] = {a0.x, a0.y, a0.z, a0.w, a1.x, a1.y, a1.z, a1.w};
            #pragma unroll
            for (int mi = 0; mi < 8; mi++) {
                ull aa = f2pack(am[mi], am[mi]);
                acc[mi][0] = f2fma(aa, b01, acc[mi][0]);
                acc[mi][1] = f2fma(aa, b23, acc[mi][1]);
            }
        }
        __syncthreads();
    }

    #pragma unroll
    for (int mi = 0; mi < 8; mi++) {
        int r = rowbase + m0 + mi;
        float2 v0 = f2unpack(acc[mi][0]);
        float2 v1 = f2unpack(acc[mi][1]);
        float4 o = make_float4(v0.x, v0.y, v1.x, v1.y);
        *(float4*)(out + (size_t)r * UNITS + nbase + n0) = o;
    }
}

// ============================================================================
// Kernel B: persistent scan. Grid (CN, CB) = 128 CTAs, one per SM.
// CTA (j, g): columns [j*64, j*64+64), batches [g*4, g*4+4).
// B slice (512x64 fp32 = 128 KB) lives in smem for all 512 steps.
// Per step: load h (8 KB) from g_h, GEMM with f32x2 + K-split over 16 segs,
// smem reduce, modrelu + xT add (in-place on d_out), publish h, group barrier.
// ============================================================================
__global__ void __launch_bounds__(NT, 1) scan_kernel(
    const float* __restrict__ Bm, const float* __restrict__ bias,
    float* __restrict__ out)
{
    extern __shared__ float smem[];
    float* Bs  = smem;                       // 512*64
    float* hs  = Bs + UNITS * CPG;           // 512*4
    float* red = hs + UNITS * BPG;           // 16*256 partials
    float* sb  = red + 16 * NT;              // 64 bias

    const int tid = threadIdx.x;
    const int j = blockIdx.x, grp = blockIdx.y;
    const int colbase = j * CPG, batchbase = grp * BPG;

    // load B slice: B[k][colbase + c]
    for (int i = tid; i < UNITS * (CPG / 4); i += NT) {
        int k = i >> 4, q = i & 15;
        *(float4*)&Bs[k * CPG + q * 4] =
            *(const float4*)(Bm + (size_t)k * UNITS + colbase + q * 4);
    }
    if (tid < CPG) sb[tid] = bias[colbase + tid];

    const int c4 = tid & 15;          // column quad (16 quads = 64 cols)
    const int ks = tid >> 4;          // k segment (16 segs of 32)
    const int kbase = ks * 32;
    const int c = tid & 63, b = tid >> 6;   // output mapping
    const int ci = c & 3, cq = c >> 2;

    float* ghp = (float*)&g_h[grp][0];
    int* barp = &g_bar[grp];
    __syncthreads();

    for (int t = 0; t < SEQ; t++) {
        const size_t oidx = ((size_t)t * BATCH + batchbase + b) * UNITS + colbase + c;
        float xv = out[oidx];   // prefetch xT early; latency hidden by GEMM

        // stage h tile: [k][4 batches]
        {
            float4* s4 = (float4*)hs;
            const float4* g4 = (const float4*)ghp;
            s4[tid] = g4[tid];
            s4[tid + NT] = g4[tid + NT];
        }
        __syncthreads();

        ull a00 = 0, a01 = 0, a02 = 0, a03 = 0;   // (b0,b1) x col 0..3
        ull a10 = 0, a11 = 0, a12 = 0, a13 = 0;   // (b2,b3) x col 0..3
        const float* bsp = Bs + c4 * 4;
        const float* hp  = hs + kbase * 4;
        #pragma unroll 8
        for (int kk = 0; kk < 32; kk++) {
            ull h01 = *(const ull*)(hp + kk * 4);
            ull h23 = *(const ull*)(hp + kk * 4 + 2);
            float4 bv = *(const float4*)(bsp + (kbase + kk) * CPG);
            ull b0 = f2pack(bv.x, bv.x), b1 = f2pack(bv.y, bv.y);
            ull b2 = f2pack(bv.z, bv.z), b3 = f2pack(bv.w, bv.w);
            a00 = f2fma(h01, b0, a00);  a10 = f2fma(h23, b0, a10);
            a01 = f2fma(h01, b1, a01);  a11 = f2fma(h23, b1, a11);
            a02 = f2fma(h01, b2, a02);  a12 = f2fma(h23, b2, a12);
            a03 = f2fma(h01, b3, a03);  a13 = f2fma(h23, b3, a13);
        }

        // partials -> red[(batch*4 + colInQuad)*256 + kslot], kslot == tid
        {
            float2 v;
            v = f2unpack(a00); red[(0*4+0)*NT + tid] = v.x; red[(1*4+0)*NT + tid] = v.y;
            v = f2unpack(a01); red[(0*4+1)*NT + tid] = v.x; red[(1*4+1)*NT + tid] = v.y;
            v = f2unpack(a02); red[(0*4+2)*NT + tid] = v.x; red[(1*4+2)*NT + tid] = v.y;
            v = f2unpack(a03); red[(0*4+3)*NT + tid] = v.x; red[(1*4+3)*NT + tid] = v.y;
            v = f2unpack(a10); red[(2*4+0)*NT + tid] = v.x; red[(3*4+0)*NT + tid] = v.y;
            v = f2unpack(a11); red[(2*4+1)*NT + tid] = v.x; red[(3*4+1)*NT + tid] = v.y;
            v = f2unpack(a12); red[(2*4+2)*NT + tid] = v.x; red[(3*4+2)*NT + tid] = v.y;
            v = f2unpack(a13); red[(2*4+3)*NT + tid] = v.x; red[(3*4+3)*NT + tid] = v.y;
        }
        __syncthreads();

        // reduce 16 k-segments for output (b, c)
        float rsum = 0.f;
        {
            const float* rp = red + (b * 4 + ci) * NT + cq;
            #pragma unroll
            for (int s = 0; s < 16; s++) rsum += rp[s * 16];
        }

        // modrelu(xT + h@B, bias)
        float z  = xv + rsum;
        float az = fabsf(z) + sb[c];
        float sgn = (z > 0.f) ? 1.f : ((z < 0.f) ? -1.f : 0.f);
        float hv = sgn * fmaxf(az, 0.f);

        out[oidx] = hv;
        ghp[(colbase + c) * BPG + b] = hv;

        __syncthreads();
        if (t < SEQ - 1) {
            if (tid == 0) {
                asm volatile("red.release.gpu.global.add.s32 [%0], 1;"
                             :: "l"(barp) : "memory");
                int target = (t + 1) * CN, v;
                do {
                    asm volatile("ld.acquire.gpu.global.s32 %0, [%1];"
                                 : "=r"(v) : "l"(barp) : "memory");
                } while (v < target);
            }
            __syncthreads();
        }
    }
}

extern "C" void kernel_launch(void* const* d_in, const int* in_sizes, int n_in,
                              void* d_out, int out_size)
{
    const float* x    = (const float*)d_in[0];
    const float* T    = (const float*)d_in[1];
    const float* Bm   = (const float*)d_in[2];
    const float* bias = (const float*)d_in[3];
    const float* h0   = (const float*)d_in[4];
    float* out = (float*)d_out;

    const int smem_bytes = (UNITS * CPG + UNITS * BPG + 16 * NT + CPG) * 4;
    cudaFuncSetAttribute(scan_kernel, cudaFuncAttributeMaxDynamicSharedMemorySize,
                         smem_bytes);

    dim3 gA(UNITS / 64, (SEQ * BATCH) / 128);   // (8, 256)
    proj_kernel<<<gA, NT>>>(x, T, h0, out);

    dim3 gB(CN, CB);                            // (8, 16) = 128 CTAs
    scan_kernel<<<gB, NT, smem_bytes>>>(Bm, bias, out);
}